// round 4
// baseline (speedup 1.0000x reference)
#include <cuda_runtime.h>

#define BATCH 8
#define SEQ   2048
#define DIM   64
#define TQ    64      // queries per CTA
#define TK    64      // keys per tile
#define NTHR  256
#define ROWP  68      // padded row stride (floats) for Q/K/V tiles

// smem floats: sQ 64*68 + sK 64*68 + sV 64*68 + sE 64*64 = 17152 floats
// + mask 2048 bytes
#define SMEM_BYTES ((64*ROWP*3 + 64*64)*4 + SEQ)

__device__ float g_inv[BATCH*SEQ];

// packed f32x2 FMA: d = a*b + d (elementwise on packed pairs)
#define FMA2(d, a, b) asm("fma.rn.f32x2 %0, %1, %2, %0;" : "+l"(d) : "l"(a), "l"(b))
__device__ __forceinline__ unsigned long long pack2(float lo, float hi) {
    unsigned long long r;
    asm("mov.b64 %0, {%1, %2};" : "=l"(r) : "f"(lo), "f"(hi));
    return r;
}
__device__ __forceinline__ float lo32(unsigned long long u) { return __uint_as_float((unsigned)u); }
__device__ __forceinline__ float hi32(unsigned long long u) { return __uint_as_float((unsigned)(u >> 32)); }

__global__ void __launch_bounds__(NTHR, 3)
attn_main_kernel(const float* __restrict__ key,
                 const float* __restrict__ query,
                 const float* __restrict__ value,
                 const int*   __restrict__ qmask,
                 float* __restrict__ out_ctx,
                 float* __restrict__ out_attn)
{
    extern __shared__ float sm[];
    float* sQ = sm;                       // [64][68]
    float* sK = sQ + 64*ROWP;             // [64][68]
    float* sV = sK + 64*ROWP;             // [64][68]
    float* sE = sV + 64*ROWP;             // [64][64]
    unsigned char* sM = (unsigned char*)(sE + 64*64);  // [2048]

    const int b  = blockIdx.y;
    const int q0 = blockIdx.x * TQ;
    const int t  = threadIdx.x;
    const int ty = t >> 4;                // 0..15 -> q rows 4*ty..+3
    const int tx = t & 15;                // 0..15

    // ---- stage Q (scaled by 1/sqrt(64) = 0.125), mask flags ----
    {
        const float4* qg = (const float4*)(query + ((size_t)b*SEQ + q0)*DIM);
        #pragma unroll
        for (int i = t; i < TQ*DIM/4; i += NTHR) {
            int r = i >> 4, c = i & 15;
            float4 v = qg[i];
            v.x *= 0.125f; v.y *= 0.125f; v.z *= 0.125f; v.w *= 0.125f;
            *(float4*)(sQ + r*ROWP + c*4) = v;
        }
        const int* mg = qmask + (size_t)b*SEQ;
        for (int i = t; i < SEQ; i += NTHR)
            sM[i] = (unsigned char)(mg[i] != 0);
    }

    unsigned long long ctx2[4][2];
    #pragma unroll
    for (int qi = 0; qi < 4; qi++) { ctx2[qi][0] = 0ull; ctx2[qi][1] = 0ull; }
    float rowsum[4] = {0.f, 0.f, 0.f, 0.f};

    const float* kg_base = key   + (size_t)b*SEQ*DIM;
    const float* vg_base = value + (size_t)b*SEQ*DIM;
    float* attn_base = out_attn + ((size_t)b*SEQ + q0)*SEQ;

    for (int kt = 0; kt < SEQ; kt += TK) {
        __syncthreads();   // prev PV / e-write done before overwriting tiles
        // ---- stage K,V tiles [64][64] -> [64][68] ----
        {
            const float4* kg = (const float4*)(kg_base + (size_t)kt*DIM);
            const float4* vg = (const float4*)(vg_base + (size_t)kt*DIM);
            #pragma unroll
            for (int i = t; i < TK*DIM/4; i += NTHR) {
                int r = i >> 4, c = i & 15;
                *(float4*)(sK + r*ROWP + c*4) = kg[i];
                *(float4*)(sV + r*ROWP + c*4) = vg[i];
            }
        }
        __syncthreads();

        // ---- QK^T: thread tile 4q x 4k (k = tx + 16j), packed f32x2 ----
        unsigned long long acc[16];
        #pragma unroll
        for (int i = 0; i < 16; i++) acc[i] = 0ull;

        #pragma unroll 4
        for (int d4 = 0; d4 < 16; d4++) {
            ulonglong2 k2[4];
            #pragma unroll
            for (int j = 0; j < 4; j++)
                k2[j] = *(const ulonglong2*)(sK + (tx + 16*j)*ROWP + d4*4);
            #pragma unroll
            for (int qi = 0; qi < 4; qi++) {
                ulonglong2 q2 = *(const ulonglong2*)(sQ + (4*ty + qi)*ROWP + d4*4);
                #pragma unroll
                for (int j = 0; j < 4; j++) {
                    FMA2(acc[qi*4 + j], q2.x, k2[j].x);
                    FMA2(acc[qi*4 + j], q2.y, k2[j].y);
                }
            }
        }
        // ---- exp + mask, STS to sE, rowsum ----
        #pragma unroll
        for (int j = 0; j < 4; j++) {
            int kk = tx + 16*j;
            unsigned char flag = sM[kt + kk];
            #pragma unroll
            for (int qi = 0; qi < 4; qi++) {
                unsigned long long a = acc[qi*4 + j];
                float s = lo32(a) + hi32(a);
                float e = flag ? 0.0f : __expf(s);
                rowsum[qi] += e;
                sE[(4*ty + qi)*64 + kk] = e;
            }
        }
        __syncthreads();

        // ---- write unnormalized e tile to gmem (coalesced) ----
        #pragma unroll
        for (int i = t; i < TQ*TK/4; i += NTHR) {
            int r = i >> 4, c = i & 15;
            float4 e4 = *(const float4*)(sE + r*64 + c*4);
            *(float4*)(attn_base + (size_t)r*SEQ + kt + c*4) = e4;
        }

        // ---- PV: ctx[4q][d=4tx..+3] += e * V ----
        #pragma unroll 2
        for (int k = 0; k < TK; k++) {
            ulonglong2 v2 = *(const ulonglong2*)(sV + k*ROWP + tx*4);
            #pragma unroll
            for (int qi = 0; qi < 4; qi++) {
                float e = sE[(4*ty + qi)*64 + k];
                unsigned long long ee = pack2(e, e);
                FMA2(ctx2[qi][0], ee, v2.x);
                FMA2(ctx2[qi][1], ee, v2.y);
            }
        }
    }

    // ---- reduce rowsums across tx (16-lane groups), write inv, store ctx ----
    #pragma unroll
    for (int qi = 0; qi < 4; qi++) {
        float s = rowsum[qi];
        #pragma unroll
        for (int o = 8; o > 0; o >>= 1)
            s += __shfl_down_sync(0xffffffffu, s, o, 16);
        s = __shfl_sync(0xffffffffu, s, 0, 16);   // broadcast group sum
        float inv = 1.0f / s;
        if (tx == 0) g_inv[(size_t)b*SEQ + q0 + 4*ty + qi] = inv;
        float4 c;
        c.x = lo32(ctx2[qi][0]) * inv;
        c.y = hi32(ctx2[qi][0]) * inv;
        c.z = lo32(ctx2[qi][1]) * inv;
        c.w = hi32(ctx2[qi][1]) * inv;
        *(float4*)(out_ctx + ((size_t)b*SEQ + q0 + 4*ty + qi)*DIM + tx*4) = c;
    }
}

// normalize attention rows: attn[row][:] *= g_inv[row]
__global__ void __launch_bounds__(256)
attn_scale_kernel(float* __restrict__ attn)
{
    const int row = blockIdx.x;
    const float s = g_inv[row];
    float4* p = (float4*)(attn + (size_t)row*SEQ);
    #pragma unroll
    for (int i = threadIdx.x; i < SEQ/4; i += 256) {
        float4 v = p[i];
        v.x *= s; v.y *= s; v.z *= s; v.w *= s;
        p[i] = v;
    }
}

extern "C" void kernel_launch(void* const* d_in, const int* in_sizes, int n_in,
                              void* d_out, int out_size)
{
    const float* key   = (const float*)d_in[0];
    const float* query = (const float*)d_in[1];
    const float* value = (const float*)d_in[2];
    const int*   qmask = (const int*)d_in[3];

    float* out_ctx  = (float*)d_out;
    float* out_attn = (float*)d_out + (size_t)BATCH*SEQ*DIM;

    cudaFuncSetAttribute(attn_main_kernel,
                         cudaFuncAttributeMaxDynamicSharedMemorySize, SMEM_BYTES);

    dim3 grid(SEQ / TQ, BATCH);
    attn_main_kernel<<<grid, NTHR, SMEM_BYTES>>>(key, query, value, qmask,
                                                 out_ctx, out_attn);
    attn_scale_kernel<<<BATCH*SEQ, 256>>>(out_attn);
}